// round 14
// baseline (speedup 1.0000x reference)
#include <cuda_runtime.h>
#include <cuda_bf16.h>
#include <cstdint>

// Problem dims (fixed by the dataset)
#define BB 32
#define SS 1024
#define II 256
#define HH 512
#define OO 256
#define MROWS (BB * SS)   // 32768
#define CSZ 2             // CTAs per batch (cluster size)
#define HSL (HH / CSZ)    // 256 columns / neurons per CTA

// Scratch (allocation-free rule: __device__ globals)
__device__ float g_ic[(size_t)MROWS * HH];   // 64 MB input currents
__device__ float g_spk[(size_t)MROWS * HH];  // 64 MB spikes (fp32 0/1)

// ---------------------------------------------------------------------------
// Register-blocked SGEMM: C[M,N] = A[M,K] @ B[K,N], all row-major fp32.
// BM=128, BN=64, BK=16, TM=8, TN=4, 256 threads (proven 211us config).
// ---------------------------------------------------------------------------
template <int BM, int BN, int BK, int TM, int TN>
__global__ __launch_bounds__(256) void sgemm_kernel(
    const float* __restrict__ A, const float* __restrict__ Bm,
    float* __restrict__ C, int M, int N, int K)
{
    __shared__ float As[BK][BM];
    __shared__ float Bs[BK][BN];

    const int tid = threadIdx.x;
    const int mBlock = blockIdx.y * BM;
    const int nBlock = blockIdx.x * BN;

    const int tCols = BN / TN;
    const int tRow = tid / tCols;
    const int tCol = tid % tCols;

    float acc[TM][TN];
#pragma unroll
    for (int i = 0; i < TM; i++)
#pragma unroll
        for (int j = 0; j < TN; j++) acc[i][j] = 0.f;

    for (int k0 = 0; k0 < K; k0 += BK) {
#pragma unroll
        for (int it = 0; it < (BM * BK) / (256 * 4); it++) {
            int f = tid + it * 256;
            int m = f / (BK / 4);
            int kq = f % (BK / 4);
            float4 v = *reinterpret_cast<const float4*>(
                &A[(size_t)(mBlock + m) * K + k0 + kq * 4]);
            As[kq * 4 + 0][m] = v.x;
            As[kq * 4 + 1][m] = v.y;
            As[kq * 4 + 2][m] = v.z;
            As[kq * 4 + 3][m] = v.w;
        }
#pragma unroll
        for (int it = 0; it < (BK * BN) / (256 * 4); it++) {
            int f = tid + it * 256;
            int k = f / (BN / 4);
            int nq = f % (BN / 4);
            float4 v = *reinterpret_cast<const float4*>(
                &Bm[(size_t)(k0 + k) * N + nBlock + nq * 4]);
            *reinterpret_cast<float4*>(&Bs[k][nq * 4]) = v;
        }
        __syncthreads();

#pragma unroll
        for (int k = 0; k < BK; k++) {
            float ra[TM], rb[TN];
#pragma unroll
            for (int i = 0; i < TM; i++) ra[i] = As[k][tRow * TM + i];
#pragma unroll
            for (int j = 0; j < TN; j++) rb[j] = Bs[k][tCol * TN + j];
#pragma unroll
            for (int i = 0; i < TM; i++)
#pragma unroll
                for (int j = 0; j < TN; j++) acc[i][j] += ra[i] * rb[j];
        }
        __syncthreads();
    }

#pragma unroll
    for (int i = 0; i < TM; i++) {
        float* crow = &C[(size_t)(mBlock + tRow * TM + i) * N + nBlock + tCol * TN];
#pragma unroll
        for (int j = 0; j < TN; j += 4) {
            float4 v = make_float4(acc[i][j], acc[i][j + 1], acc[i][j + 2], acc[i][j + 3]);
            *reinterpret_cast<float4*>(&crow[j]) = v;
        }
    }
}

// ---------------------------------------------------------------------------
// PTX helpers
// ---------------------------------------------------------------------------
__device__ __forceinline__ uint32_t smem_addr_u32(const void* p) {
    uint32_t a;
    asm("{ .reg .u64 t; cvta.to.shared.u64 t, %1; cvt.u32.u64 %0, t; }"
        : "=r"(a) : "l"(p));
    return a;
}

__device__ __forceinline__ uint32_t mapa_u32(uint32_t laddr, uint32_t rank) {
    uint32_t r;
    asm("mapa.shared::cluster.u32 %0, %1, %2;" : "=r"(r) : "r"(laddr), "r"(rank));
    return r;
}

__device__ __forceinline__ void st_cluster_weak_u32(uint32_t raddr, uint32_t v) {
    asm volatile("st.shared::cluster.u32 [%0], %1;" :: "r"(raddr), "r"(v) : "memory");
}

__device__ __forceinline__ void st_cluster_release_u32(uint32_t raddr, uint32_t v) {
    asm volatile("st.release.cluster.shared::cluster.u32 [%0], %1;"
                 :: "r"(raddr), "r"(v) : "memory");
}

__device__ __forceinline__ uint32_t ld_acquire_cluster_u32(uint32_t laddr) {
    uint32_t v;
    asm volatile("ld.acquire.cluster.shared::cta.u32 %0, [%1];"
                 : "=r"(v) : "r"(laddr) : "memory");
    return v;
}

// ---------------------------------------------------------------------------
// 2-CTA-cluster recurrent scan. 32 clusters (one per batch) x 2 CTAs x 512 thr.
// CTA `rank` owns neurons [rank*256, rank*256+256) and W_lat columns
// [rank*256, rank*256+256): per-step gather traffic is HALVED per SM
// (ns rows x 1KB = ns x 8 L1 wavefronts vs ns x 16 single-CTA).
// Cross-CTA exchange per step: one courier thread sends this CTA's 8 ballot
// words via weak DSMEM stores (pipelined, one ~215cyc latency) + one
// st.release flag; peers spin with ld.acquire on their OWN smem. No
// cluster.sync in the loop => no CCTL.IVALL, L1 stays warm.
// Masks double-buffered by parity; flag values monotonic (t+1).
// ---------------------------------------------------------------------------
__global__ void __cluster_dims__(CSZ, 1, 1) __launch_bounds__(512, 1)
snn_scan_kernel(
    const float* __restrict__ ic, const float* __restrict__ Wlat,
    const float* __restrict__ thr, float* __restrict__ spk)
{
    __shared__ float part_s[2][HSL];          // [shard][column] partials
    __shared__ unsigned masks_all[2][16];     // [parity][global word 0..15]
    __shared__ unsigned flag_s[2];            // [parity] peer-progress flag
    __shared__ int list_s[HH];

    const int tid = threadIdx.x;              // 0..511
    const int lane = tid & 31;
    const int warp = tid >> 5;                // 0..15
    const int shard = tid >> 8;               // 0..1 (gather shard)
    const int ctid = tid & (HSL - 1);         // 0..255 (column within slice)
    const int b = blockIdx.x / CSZ;
    uint32_t rank;
    asm("mov.u32 %0, %%cluster_ctarank;" : "=r"(rank));
    const uint32_t peer = rank ^ 1u;

    if (tid < 2) flag_s[tid] = 0u;
    __syncthreads();
    // Publish flag init before any remote store can land.
    asm volatile("barrier.cluster.arrive.aligned;" ::: "memory");
    asm volatile("barrier.cluster.wait.aligned;" ::: "memory");

    const bool owner = (tid < HSL);           // warps 0..7 own neurons
    const int h = (int)rank * HSL + tid;      // global neuron (owners)
    const float thrv = owner ? thr[h] : 0.f;

    float mp = 0.f;
    int refrac = 0;
    int ns = 0;
    const size_t rowbase = (size_t)b * SS * HH;
    float ic_cur = owner ? ic[rowbase + h] : 0.f;

    // This thread's W_lat column pointer (coalesced across ctid).
    const float* Wcol = Wlat + (size_t)rank * HSL + ctid;

    for (int t = 0; t < SS; ++t) {
        float ic_nxt = (owner && t < SS - 1) ? ic[rowbase + (size_t)(t + 1) * HH + h] : 0.f;

        // --- gather: shard walks alternate list entries, 4 indep accumulators ---
        float a0 = 0.f, a1 = 0.f, a2 = 0.f, a3 = 0.f;
        int k = shard;
        for (; k + 6 < ns; k += 8) {
            int j0 = list_s[k];
            int j1 = list_s[k + 2];
            int j2 = list_s[k + 4];
            int j3 = list_s[k + 6];
            a0 += Wcol[(size_t)j0 * HH];
            a1 += Wcol[(size_t)j1 * HH];
            a2 += Wcol[(size_t)j2 * HH];
            a3 += Wcol[(size_t)j3 * HH];
        }
        for (; k < ns; k += 2) a0 += Wcol[(size_t)list_s[k] * HH];
        part_s[shard][ctid] = (a0 + a1) + (a2 + a3);
        __syncthreads();                                   // S1

        const int p = t & 1;

        if (owner) {
            float lat = part_s[0][tid] + part_s[1][tid];

            // --- membrane update (reference semantics, fp32) ---
            mp = 0.95f * mp + ic_cur - lat;
            if (refrac > 0) mp = 0.f;
            refrac = (refrac > 0) ? (refrac - 1) : 0;
            bool spike = (mp >= thrv);
            spk[rowbase + (size_t)t * HH + h] = spike ? 1.f : 0.f;
            if (spike) { mp = 0.f; refrac = 2; }

            unsigned m = __ballot_sync(0xffffffffu, spike);
            if (lane == 0) masks_all[p][rank * 8 + warp] = m;
        }
        __syncthreads();                                   // S2: local masks ready

        // --- courier: ship my 8 words + release flag to the peer ---
        if (tid == 0) {
            uint32_t lbase = smem_addr_u32(&masks_all[p][rank * 8]);
            uint32_t rbase = mapa_u32(lbase, peer);
            unsigned w0 = masks_all[p][rank * 8 + 0];
            unsigned w1 = masks_all[p][rank * 8 + 1];
            unsigned w2 = masks_all[p][rank * 8 + 2];
            unsigned w3 = masks_all[p][rank * 8 + 3];
            unsigned w4 = masks_all[p][rank * 8 + 4];
            unsigned w5 = masks_all[p][rank * 8 + 5];
            unsigned w6 = masks_all[p][rank * 8 + 6];
            unsigned w7 = masks_all[p][rank * 8 + 7];
            st_cluster_weak_u32(rbase + 0, w0);
            st_cluster_weak_u32(rbase + 4, w1);
            st_cluster_weak_u32(rbase + 8, w2);
            st_cluster_weak_u32(rbase + 12, w3);
            st_cluster_weak_u32(rbase + 16, w4);
            st_cluster_weak_u32(rbase + 20, w5);
            st_cluster_weak_u32(rbase + 24, w6);
            st_cluster_weak_u32(rbase + 28, w7);
            uint32_t lflag = smem_addr_u32(&flag_s[p]);
            uint32_t rflag = mapa_u32(lflag, peer);
            st_cluster_release_u32(rflag, (uint32_t)(t + 1));
        }

        // --- spin until the peer's step-t masks have landed ---
        {
            uint32_t fl = smem_addr_u32(&flag_s[p]);
            while (ld_acquire_cluster_u32(fl) < (uint32_t)(t + 1)) { }
        }

        // --- rebuild full 512-neuron firing list from 16 global words ---
        unsigned wm[16];
        int pref[16];
        int tot = 0;
#pragma unroll
        for (int w = 0; w < 16; ++w) {
            wm[w] = masks_all[p][w];
            pref[w] = tot;
            tot += __popc(wm[w]);
        }
        {
            unsigned mw = wm[warp];           // thread tid = global neuron tid
            if (mw & (1u << lane)) {
                int pos = pref[warp] + __popc(mw & ((1u << lane) - 1u));
                list_s[pos] = tid;
            }
        }
        ns = tot;
        ic_cur = ic_nxt;
        __syncthreads();                                   // S3: list visible
    }

    // No CTA exits while the peer may still store into its smem.
    asm volatile("barrier.cluster.arrive.aligned;" ::: "memory");
    asm volatile("barrier.cluster.wait.aligned;" ::: "memory");
}

// ---------------------------------------------------------------------------
// Launch
// ---------------------------------------------------------------------------
extern "C" void kernel_launch(void* const* d_in, const int* in_sizes, int n_in,
                              void* d_out, int out_size)
{
    const float* x    = (const float*)d_in[0];  // [B,S,I]
    const float* Win  = (const float*)d_in[1];  // [I,H]
    const float* Wlat = (const float*)d_in[2];  // [H,H]
    const float* Wout = (const float*)d_in[3];  // [H,O]
    const float* thr  = (const float*)d_in[4];  // [H]
    float* out = (float*)d_out;                 // [B,S,O]

    float *ic, *spk;
    cudaGetSymbolAddress((void**)&ic, g_ic);
    cudaGetSymbolAddress((void**)&spk, g_spk);

    // GEMM1: ic = x @ Win   (32768 x 512 x 256)
    {
        dim3 grid(HH / 64, MROWS / 128);
        sgemm_kernel<128, 64, 16, 8, 4><<<grid, 256>>>(x, Win, ic, MROWS, HH, II);
    }

    // Scan: 32 clusters x 2 CTAs x 512 threads
    snn_scan_kernel<<<BB * CSZ, 512>>>(ic, Wlat, thr, spk);

    // GEMM3: out = spk @ Wout   (32768 x 256 x 512)
    {
        dim3 grid(OO / 64, MROWS / 128);
        sgemm_kernel<128, 64, 16, 8, 4><<<grid, 256>>>(spk, Wout, out, MROWS, OO, HH);
    }
}